// round 3
// baseline (speedup 1.0000x reference)
#include <cuda_runtime.h>
#include <cstdint>

// Residual quantizer, fp32, arithmetic mirror of JAX/XLA-CPU reference
// (validated round 2: rel_err 7.35e-4). This round: register-tiled GEMM for
// the distance pass. 256 threads = 64 point-groups x 4 code-groups; each
// thread accumulates a 4-point x 16-code tile as 32 packed fma.rn.f32x2
// chains (lanes = code pairs), sequential over the 64 dims -> bitwise
// identical dot products to the 1-point/thread version, ~6x less LDS/MAC.
// Residual in SMEM [dim][point], codebook transposed [dim][code].

#define KCODES 256
#define DIM 64
#define LEVELS 4
#define PTS 256
#define ROWS 260                 // padded floats per dim-row
#define ROWB (ROWS * 4)          // 1040 B, 16B aligned
// floats: R 64*260 + C 64*260 + c2 256 ; ints: k_sm 256 + idx_all 1024
#define SMEM_BYTES ((2 * DIM * ROWS + KCODES) * 4 + (PTS + LEVELS * PTS) * 4)

#define FMA2(d, a, b, c) \
    asm("fma.rn.f32x2 %0, %1, %2, %3;" : "=l"(d) : "l"(a), "l"(b), "l"(c))
#define DUP2(d, s) asm("mov.b64 %0, {%1, %1};" : "=l"(d) : "f"(s))
#define LDS_V2U64(a, b, addr) \
    asm("ld.shared.v2.u64 {%0,%1}, [%2];" : "=l"(a), "=l"(b) : "r"(addr))

__global__ void __launch_bounds__(256, 1)
rq_kernel(const float* __restrict__ z, const float* __restrict__ cb,
          float* __restrict__ out, int B) {
    extern __shared__ __align__(16) float smem[];
    float* R  = smem;                    // [dim][point], stride ROWS
    float* C  = smem + DIM * ROWS;       // [dim][code],  stride ROWS
    float* c2 = C + DIM * ROWS;          // [256]
    int* k_sm    = (int*)(c2 + KCODES);  // [256] chosen code per point
    int* idx_all = k_sm + PTS;           // [LEVELS][256]

    const int tid = threadIdx.x;
    const int pg  = tid >> 2;            // point-group 0..63 (4 points each)
    const int kg  = tid & 3;             // code-group  0..3
    const long myp_raw = (long)blockIdx.x * PTS + tid;
    const long myp = myp_raw < B ? myp_raw : (B - 1);

    // ---- init residual R[j][tid] = z[myp][j] ----
    {
        const float4* zp = reinterpret_cast<const float4*>(z + myp * DIM);
#pragma unroll
        for (int i = 0; i < 16; i++) {
            float4 v = zp[i];
            R[(4 * i + 0) * ROWS + tid] = v.x;
            R[(4 * i + 1) * ROWS + tid] = v.y;
            R[(4 * i + 2) * ROWS + tid] = v.z;
            R[(4 * i + 3) * ROWS + tid] = v.w;
        }
    }

    const unsigned smR = (unsigned)__cvta_generic_to_shared(R);
    const unsigned smC = (unsigned)__cvta_generic_to_shared(C);

#pragma unroll 1
    for (int lvl = 0; lvl < LEVELS; lvl++) {
        __syncthreads();   // protects C (prev level's update read it) & R
        // ---- stage codebook level transposed: C[j][tid] = cb[lvl][tid][j]
        {
            const float4* src = reinterpret_cast<const float4*>(
                cb + ((size_t)lvl * KCODES + tid) * DIM);
#pragma unroll
            for (int i = 0; i < 16; i++) {
                float4 v = src[i];
                C[(4 * i + 0) * ROWS + tid] = v.x;
                C[(4 * i + 1) * ROWS + tid] = v.y;
                C[(4 * i + 2) * ROWS + tid] = v.z;
                C[(4 * i + 3) * ROWS + tid] = v.w;
            }
        }
        __syncthreads();
        // ---- c2[k]: square-then-add, sequential over dims ----
        {
            float s = 0.f;
#pragma unroll
            for (int j = 0; j < DIM; j++) {
                float c = C[j * ROWS + tid];
                s = __fadd_rn(s, __fmul_rn(c, c));
            }
            c2[tid] = s;
        }
        __syncthreads();

        // ---- r2 for my 4 points (sequential chains) ----
        float r2v[4];
        {
            float s0 = 0.f, s1 = 0.f, s2 = 0.f, s3 = 0.f;
#pragma unroll
            for (int j = 0; j < DIM; j++) {
                const float4 rv =
                    *reinterpret_cast<const float4*>(R + j * ROWS + pg * 4);
                s0 = __fadd_rn(s0, __fmul_rn(rv.x, rv.x));
                s1 = __fadd_rn(s1, __fmul_rn(rv.y, rv.y));
                s2 = __fadd_rn(s2, __fmul_rn(rv.z, rv.z));
                s3 = __fadd_rn(s3, __fmul_rn(rv.w, rv.w));
            }
            r2v[0] = s0; r2v[1] = s1; r2v[2] = s2; r2v[3] = s3;
        }

        float best[4];
        int bi[4];
#pragma unroll
        for (int i = 0; i < 4; i++) {
            best[i] = __int_as_float(0x7F800000);
            bi[i] = 0;
        }

        const unsigned rAddr = smR + pg * 16;
        // ---- tiled distance pass: 4 kiters x (4 pts x 16 codes) ----
#pragma unroll 1
        for (int kiter = 0; kiter < 4; kiter++) {
            const int kbase = kiter * 64 + kg * 16;
            const unsigned cAddr = smC + kbase * 4;
            unsigned long long acc[4][8];
#pragma unroll
            for (int i = 0; i < 4; i++)
#pragma unroll
                for (int m = 0; m < 8; m++) acc[i][m] = 0ULL;

#pragma unroll 8
            for (int j = 0; j < DIM; j++) {
                float rx, ry, rz, rw;
                asm("ld.shared.v4.f32 {%0,%1,%2,%3}, [%4];"
                    : "=f"(rx), "=f"(ry), "=f"(rz), "=f"(rw)
                    : "r"(rAddr + j * ROWB));
                unsigned long long rb[4];
                DUP2(rb[0], rx); DUP2(rb[1], ry);
                DUP2(rb[2], rz); DUP2(rb[3], rw);
                unsigned long long cr[8];
                const unsigned ca = cAddr + j * ROWB;
                LDS_V2U64(cr[0], cr[1], ca);
                LDS_V2U64(cr[2], cr[3], ca + 16);
                LDS_V2U64(cr[4], cr[5], ca + 32);
                LDS_V2U64(cr[6], cr[7], ca + 48);
#pragma unroll
                for (int i = 0; i < 4; i++)
#pragma unroll
                    for (int m = 0; m < 8; m++)
                        FMA2(acc[i][m], rb[i], cr[m], acc[i][m]);
            }
            // ---- distances + local argmin (ascending k => first-min) ----
#pragma unroll
            for (int i = 0; i < 4; i++) {
#pragma unroll
                for (int m = 0; m < 8; m++) {
                    float lo, hi;
                    asm("mov.b64 {%0,%1}, %2;"
                        : "=f"(lo), "=f"(hi) : "l"(acc[i][m]));
                    const int k0 = kbase + 2 * m;
                    float d0 = __fadd_rn(
                        __fsub_rn(r2v[i], __fmul_rn(2.0f, lo)), c2[k0]);
                    float d1 = __fadd_rn(
                        __fsub_rn(r2v[i], __fmul_rn(2.0f, hi)), c2[k0 + 1]);
                    if (d0 < best[i]) { best[i] = d0; bi[i] = k0; }
                    if (d1 < best[i]) { best[i] = d1; bi[i] = k0 + 1; }
                }
            }
        }

        // ---- cross-code-group argmin reduce (tie -> lowest index) ----
#pragma unroll
        for (int i = 0; i < 4; i++) {
#pragma unroll
            for (int off = 1; off <= 2; off <<= 1) {
                float ob = __shfl_xor_sync(0xffffffffu, best[i], off);
                int obi  = __shfl_xor_sync(0xffffffffu, bi[i], off);
                if (ob < best[i] || (ob == best[i] && obi < bi[i])) {
                    best[i] = ob; bi[i] = obi;
                }
            }
        }
        if (kg == 0) {
#pragma unroll
            for (int i = 0; i < 4; i++) {
                k_sm[pg * 4 + i] = bi[i];
                idx_all[lvl * PTS + pg * 4 + i] = bi[i];
            }
        }
        __syncthreads();

        // ---- residual update: thread tid owns point tid ----
        {
            const int k = k_sm[tid];
#pragma unroll
            for (int j = 0; j < DIM; j++)
                R[j * ROWS + tid] =
                    __fsub_rn(R[j * ROWS + tid], C[j * ROWS + k]);
        }
    }
    __syncthreads();

    if (myp_raw >= B) return;

    // ---- epilogue: quantized = ((q0+q1)+q2)+q3, gathered from gmem ----
    int id[LEVELS];
#pragma unroll
    for (int lvl = 0; lvl < LEVELS; lvl++) id[lvl] = idx_all[lvl * PTS + tid];

    float q[DIM];
#pragma unroll
    for (int j = 0; j < DIM; j++) q[j] = 0.f;
#pragma unroll 1
    for (int lvl = 0; lvl < LEVELS; lvl++) {
        const float4* cp = reinterpret_cast<const float4*>(
            cb + ((size_t)lvl * KCODES + id[lvl]) * DIM);
#pragma unroll
        for (int i = 0; i < 16; i++) {
            float4 v = cp[i];
            q[4 * i + 0] = __fadd_rn(q[4 * i + 0], v.x);
            q[4 * i + 1] = __fadd_rn(q[4 * i + 1], v.y);
            q[4 * i + 2] = __fadd_rn(q[4 * i + 2], v.z);
            q[4 * i + 3] = __fadd_rn(q[4 * i + 3], v.w);
        }
    }

    const float4* zp = reinterpret_cast<const float4*>(z + myp * DIM);
    float4* qst = reinterpret_cast<float4*>(out + (size_t)myp * DIM);
    float4* qq  = reinterpret_cast<float4*>(out + (size_t)B * (DIM + 4) +
                                            (size_t)myp * DIM);
#pragma unroll
    for (int i = 0; i < 16; i++) {
        float4 zv = zp[i];
        float4 qv = make_float4(q[4 * i + 0], q[4 * i + 1],
                                q[4 * i + 2], q[4 * i + 3]);
        float4 sv;
        sv.x = __fadd_rn(zv.x, __fsub_rn(qv.x, zv.x));
        sv.y = __fadd_rn(zv.y, __fsub_rn(qv.y, zv.y));
        sv.z = __fadd_rn(zv.z, __fsub_rn(qv.z, zv.z));
        sv.w = __fadd_rn(zv.w, __fsub_rn(qv.w, zv.w));
        qst[i] = sv;
        qq[i] = qv;
    }
    float4 iv;
    iv.x = (float)id[0]; iv.y = (float)id[1];
    iv.z = (float)id[2]; iv.w = (float)id[3];
    reinterpret_cast<float4*>(out + (size_t)B * DIM)[myp] = iv;
}

extern "C" void kernel_launch(void* const* d_in, const int* in_sizes, int n_in,
                              void* d_out, int out_size) {
    const float* z = (const float*)d_in[0];
    const float* cb = (const float*)d_in[1];
    float* out = (float*)d_out;
    int B = in_sizes[0] / DIM;

    cudaFuncSetAttribute(rq_kernel, cudaFuncAttributeMaxDynamicSharedMemorySize,
                         SMEM_BYTES);
    int blocks = (B + PTS - 1) / PTS;
    rq_kernel<<<blocks, PTS, SMEM_BYTES>>>(z, cb, out, B);
}

// round 4
// speedup vs baseline: 1.4124x; 1.4124x over previous
#include <cuda_runtime.h>
#include <cstdint>

// Residual quantizer, fp32, arithmetic mirror of the reference (validated:
// rel_err 7.35e-4). Round 4: warp-uniform codebook loads. 256 threads own
// 2 points each (512 pts/block); every lane of a warp processes the SAME
// 16-code tile per iteration, so codebook smem loads are broadcasts (1
// wavefront) instead of per-lane-distinct 16B loads (4 wavefronts + bank
// conflicts) that capped rounds 2-3 at L1=94%. Each thread runs all 256
// codes for its own points -> thread-local argmin, no reduction, indices
// in registers. All FMA chains bitwise identical to the passing kernel.

#define KCODES 256
#define DIM 64
#define LEVELS 4
#define NPTS 512                 // points per block
#define RST 512                  // R row stride (floats)
#define CST 260                  // C row stride (floats), 1040 B rows
#define R_BYTES (DIM * RST * 4)              // 131072
#define C_BYTES (DIM * CST * 4)              // 66560
#define SMEM_BYTES (R_BYTES + C_BYTES + KCODES * 4)   // 198656

#define FMA2(d, a, b, c) \
    asm("fma.rn.f32x2 %0, %1, %2, %3;" : "=l"(d) : "l"(a), "l"(b), "l"(c))
#define DUP2(d, s) asm("mov.b64 %0, {%1, %1};" : "=l"(d) : "f"(s))
#define LDS_V2U64(a, b, addr) \
    asm("ld.shared.v2.u64 {%0,%1}, [%2];" : "=l"(a), "=l"(b) : "r"(addr))

__global__ void __launch_bounds__(256, 1)
rq_kernel(const float* __restrict__ z, const float* __restrict__ cb,
          float* __restrict__ out, int B) {
    extern __shared__ __align__(16) char sm_raw[];
    float* R  = reinterpret_cast<float*>(sm_raw);
    float* C  = reinterpret_cast<float*>(sm_raw + R_BYTES);
    float* c2 = reinterpret_cast<float*>(sm_raw + R_BYTES + C_BYTES);

    const int tid = threadIdx.x;
    const int lp0 = 2 * tid;                    // my two local points
    const long p0_raw = (long)blockIdx.x * NPTS + lp0;
    const long p0 = p0_raw < B ? p0_raw : (B - 1);
    const long p1 = (p0_raw + 1) < B ? (p0_raw + 1) : (B - 1);

    // ---- init residual R[j][lp0..lp0+1] = z ----
    {
        const float4* z0 = reinterpret_cast<const float4*>(z + p0 * DIM);
        const float4* z1 = reinterpret_cast<const float4*>(z + p1 * DIM);
#pragma unroll
        for (int i = 0; i < 16; i++) {
            float4 a = z0[i], b = z1[i];
            *reinterpret_cast<float2*>(R + (4 * i + 0) * RST + lp0) =
                make_float2(a.x, b.x);
            *reinterpret_cast<float2*>(R + (4 * i + 1) * RST + lp0) =
                make_float2(a.y, b.y);
            *reinterpret_cast<float2*>(R + (4 * i + 2) * RST + lp0) =
                make_float2(a.z, b.z);
            *reinterpret_cast<float2*>(R + (4 * i + 3) * RST + lp0) =
                make_float2(a.w, b.w);
        }
    }

    const unsigned smR = (unsigned)__cvta_generic_to_shared(R) + lp0 * 4;
    const unsigned smC = (unsigned)__cvta_generic_to_shared(C);

    int id0[LEVELS], id1[LEVELS];

#pragma unroll 1
    for (int lvl = 0; lvl < LEVELS; lvl++) {
        __syncthreads();   // prev level's residual update read C
        // ---- stage codebook level transposed: C[j][tid] = cb[lvl][tid][j]
        {
            const float4* src = reinterpret_cast<const float4*>(
                cb + ((size_t)lvl * KCODES + tid) * DIM);
#pragma unroll
            for (int i = 0; i < 16; i++) {
                float4 v = src[i];
                C[(4 * i + 0) * CST + tid] = v.x;
                C[(4 * i + 1) * CST + tid] = v.y;
                C[(4 * i + 2) * CST + tid] = v.z;
                C[(4 * i + 3) * CST + tid] = v.w;
            }
        }
        __syncthreads();
        // ---- c2[k]: square-then-add, sequential over dims ----
        {
            float s = 0.f;
#pragma unroll
            for (int j = 0; j < DIM; j++) {
                float c = C[j * CST + tid];
                s = __fadd_rn(s, __fmul_rn(c, c));
            }
            c2[tid] = s;
        }
        __syncthreads();

        // ---- r2 for my 2 points (sequential chains) ----
        float r2a = 0.f, r2b = 0.f;
#pragma unroll
        for (int j = 0; j < DIM; j++) {
            float2 rv = *reinterpret_cast<const float2*>(R + j * RST + lp0);
            r2a = __fadd_rn(r2a, __fmul_rn(rv.x, rv.x));
            r2b = __fadd_rn(r2b, __fmul_rn(rv.y, rv.y));
        }

        float best0 = __int_as_float(0x7F800000);
        float best1 = __int_as_float(0x7F800000);
        int bi0 = 0, bi1 = 0;

        // ---- distance pass: 16 tiles of 16 codes, warp-uniform code loads
#pragma unroll 1
        for (int kt = 0; kt < 16; kt++) {
            const unsigned cA = smC + kt * 64;   // 16 codes * 4 B
            unsigned long long a0[8], a1[8];
#pragma unroll
            for (int m = 0; m < 8; m++) { a0[m] = 0ULL; a1[m] = 0ULL; }

#pragma unroll 8
            for (int j = 0; j < DIM; j++) {
                float rx, ry;
                asm("ld.shared.v2.f32 {%0,%1}, [%2];"
                    : "=f"(rx), "=f"(ry) : "r"(smR + j * (RST * 4)));
                unsigned long long ra, rb;
                DUP2(ra, rx); DUP2(rb, ry);
                unsigned long long c[8];
                const unsigned ca = cA + j * (CST * 4);
                LDS_V2U64(c[0], c[1], ca);
                LDS_V2U64(c[2], c[3], ca + 16);
                LDS_V2U64(c[4], c[5], ca + 32);
                LDS_V2U64(c[6], c[7], ca + 48);
#pragma unroll
                for (int m = 0; m < 8; m++) FMA2(a0[m], ra, c[m], a0[m]);
#pragma unroll
                for (int m = 0; m < 8; m++) FMA2(a1[m], rb, c[m], a1[m]);
            }
            // ---- distances + argmin (ascending k, strict < => first-min)
#pragma unroll
            for (int m = 0; m < 8; m++) {
                const int k0 = kt * 16 + 2 * m;
                const float cc0 = c2[k0], cc1 = c2[k0 + 1];
                float lo, hi;
                asm("mov.b64 {%0,%1}, %2;" : "=f"(lo), "=f"(hi) : "l"(a0[m]));
                float d0 = __fadd_rn(__fsub_rn(r2a, __fmul_rn(2.0f, lo)), cc0);
                float d1 = __fadd_rn(__fsub_rn(r2a, __fmul_rn(2.0f, hi)), cc1);
                if (d0 < best0) { best0 = d0; bi0 = k0; }
                if (d1 < best0) { best0 = d1; bi0 = k0 + 1; }
                asm("mov.b64 {%0,%1}, %2;" : "=f"(lo), "=f"(hi) : "l"(a1[m]));
                float e0 = __fadd_rn(__fsub_rn(r2b, __fmul_rn(2.0f, lo)), cc0);
                float e1 = __fadd_rn(__fsub_rn(r2b, __fmul_rn(2.0f, hi)), cc1);
                if (e0 < best1) { best1 = e0; bi1 = k0; }
                if (e1 < best1) { best1 = e1; bi1 = k0 + 1; }
            }
        }
        id0[lvl] = bi0; id1[lvl] = bi1;

        // ---- residual update for my own points (reads C; sync at loop top)
#pragma unroll
        for (int j = 0; j < DIM; j++) {
            float2 rv = *reinterpret_cast<const float2*>(R + j * RST + lp0);
            rv.x = __fsub_rn(rv.x, C[j * CST + bi0]);
            rv.y = __fsub_rn(rv.y, C[j * CST + bi1]);
            *reinterpret_cast<float2*>(R + j * RST + lp0) = rv;
        }
    }

    // ---- epilogue: quantized = ((q0+q1)+q2)+q3 from gmem gathers ----
    const long pts[2] = {p0, p1};
    const int* ids[2] = {id0, id1};
    const bool valid[2] = {p0_raw < B, (p0_raw + 1) < B};
#pragma unroll 1
    for (int s = 0; s < 2; s++) {
        if (!valid[s]) continue;
        const long p = pts[s];
        float q[DIM];
#pragma unroll
        for (int j = 0; j < DIM; j++) q[j] = 0.f;
#pragma unroll 1
        for (int lvl = 0; lvl < LEVELS; lvl++) {
            const float4* cp = reinterpret_cast<const float4*>(
                cb + ((size_t)lvl * KCODES + ids[s][lvl]) * DIM);
#pragma unroll
            for (int i = 0; i < 16; i++) {
                float4 v = cp[i];
                q[4 * i + 0] = __fadd_rn(q[4 * i + 0], v.x);
                q[4 * i + 1] = __fadd_rn(q[4 * i + 1], v.y);
                q[4 * i + 2] = __fadd_rn(q[4 * i + 2], v.z);
                q[4 * i + 3] = __fadd_rn(q[4 * i + 3], v.w);
            }
        }
        const float4* zp = reinterpret_cast<const float4*>(z + p * DIM);
        float4* qst = reinterpret_cast<float4*>(out + (size_t)p * DIM);
        float4* qq  = reinterpret_cast<float4*>(out + (size_t)B * (DIM + 4) +
                                                (size_t)p * DIM);
#pragma unroll
        for (int i = 0; i < 16; i++) {
            float4 zv = zp[i];
            float4 qv = make_float4(q[4 * i + 0], q[4 * i + 1],
                                    q[4 * i + 2], q[4 * i + 3]);
            float4 sv;
            sv.x = __fadd_rn(zv.x, __fsub_rn(qv.x, zv.x));
            sv.y = __fadd_rn(zv.y, __fsub_rn(qv.y, zv.y));
            sv.z = __fadd_rn(zv.z, __fsub_rn(qv.z, zv.z));
            sv.w = __fadd_rn(zv.w, __fsub_rn(qv.w, zv.w));
            qst[i] = sv;
            qq[i] = qv;
        }
        float4 iv;
        iv.x = (float)ids[s][0]; iv.y = (float)ids[s][1];
        iv.z = (float)ids[s][2]; iv.w = (float)ids[s][3];
        reinterpret_cast<float4*>(out + (size_t)B * DIM)[p] = iv;
    }
}

extern "C" void kernel_launch(void* const* d_in, const int* in_sizes, int n_in,
                              void* d_out, int out_size) {
    const float* z = (const float*)d_in[0];
    const float* cb = (const float*)d_in[1];
    float* out = (float*)d_out;
    int B = in_sizes[0] / DIM;

    cudaFuncSetAttribute(rq_kernel, cudaFuncAttributeMaxDynamicSharedMemorySize,
                         SMEM_BYTES);
    int blocks = (B + NPTS - 1) / NPTS;
    rq_kernel<<<blocks, 256, SMEM_BYTES>>>(z, cb, out, B);
}